// round 16
// baseline (speedup 1.0000x reference)
#include <cuda_runtime.h>
#include <cuda_bf16.h>
#include <math.h>

#define NIMG 1024
typedef unsigned int u32;

// ---------------------------------------------------------------------------
// scratch
// ---------------------------------------------------------------------------
__device__ __align__(128) u32 g_w1f[16 * 4 * 64];
__device__ __align__(128) u32 g_w2f[32 * 8 * 64];
__device__ __align__(128) u32 g_w3f[36 * 8 * 64];
__device__ __align__(128) u32 g_wfc[196 * 32 * 64];
__device__ __align__(128) u32 g_we1[16 * 32 * 64];
__device__ __align__(128) u32 g_we2[16 * 8 * 64];
__device__ __align__(128) u32 g_wp1[16 * 32 * 64];
__device__ __align__(128) __nv_bfloat16 g_a1[(size_t)NIMG * 12800];   // NHWC [img][400][32]
__device__ __align__(128) __nv_bfloat16 g_a2n[(size_t)NIMG * 81 * 64];
__device__ __align__(128) __nv_bfloat16 g_feat[(size_t)NIMG * 3136];
__device__ __align__(128) float g_h1[NIMG * 256];
__device__ __align__(128) float g_phi[NIMG * 64];
__device__ __align__(128) float g_hp[512 * 256];
__device__ __align__(128) float g_cy[512];
__device__ __align__(128) float g_lse[512];
__device__ __align__(128) float g_diag[512];
__device__ __align__(128) float g_part[4 * 1024 * 256];
__device__ int g_done = 0;

// ---------------------------------------------------------------------------
// helpers
// ---------------------------------------------------------------------------
__device__ __forceinline__ u32 packbf(float lo, float hi) {
    __nv_bfloat162 h = __float22bfloat162_rn(make_float2(lo, hi));
    return *reinterpret_cast<u32*>(&h);
}
__device__ __forceinline__ void mmabf(float* d, const u32* a, const u32* b) {
    asm volatile(
        "mma.sync.aligned.m16n8k16.row.col.f32.bf16.bf16.f32 "
        "{%0,%1,%2,%3},{%4,%5,%6,%7},{%8,%9},{%0,%1,%2,%3};\n"
        : "+f"(d[0]), "+f"(d[1]), "+f"(d[2]), "+f"(d[3])
        : "r"(a[0]), "r"(a[1]), "r"(a[2]), "r"(a[3]), "r"(b[0]), "r"(b[1]));
}
__device__ __forceinline__ void ldsm4(u32* r, u32 addr) {
    asm volatile("ldmatrix.sync.aligned.m8n8.x4.shared.b16 {%0,%1,%2,%3}, [%4];"
                 : "=r"(r[0]), "=r"(r[1]), "=r"(r[2]), "=r"(r[3]) : "r"(addr));
}
__device__ __forceinline__ u32 smem_u32(const void* p) {
    u32 a;
    asm("{ .reg .u64 t; cvta.to.shared.u64 t, %1; cvt.u32.u64 %0, t; }"
        : "=r"(a) : "l"(p));
    return a;
}
__device__ __forceinline__ void cpa16(u32 saddr, const void* g) {
    asm volatile("cp.async.ca.shared.global [%0], [%1], 16;"
                 :: "r"(saddr), "l"(g));
}
__device__ __forceinline__ void cpa_commit() {
    asm volatile("cp.async.commit_group;");
}
template<int N> __device__ __forceinline__ void cpa_wait() {
    asm volatile("cp.async.wait_group %0;" :: "n"(N));
}

// ---------------------------------------------------------------------------
// unified weight prep (blocks 0..439 scalar, 440..537 tiled fcw)
// conv2 frag layout: chunk c = pos*2 + h (pos = ky*4+kx), k-within = ic.
// ---------------------------------------------------------------------------
__global__ void prep_all(const float* __restrict__ c1w, const float* __restrict__ c2w,
                         const float* __restrict__ c3w, const float* __restrict__ fcw,
                         const float* __restrict__ e1w, const float* __restrict__ e2w,
                         const float* __restrict__ pw1,
                         u32* __restrict__ w1f, u32* __restrict__ w2f,
                         u32* __restrict__ w3f, u32* __restrict__ wfc,
                         u32* __restrict__ we1, u32* __restrict__ we2,
                         u32* __restrict__ wp1) {
    __shared__ float S[32 * 257];
    const int b = blockIdx.x;
    if (b < 440) {
        int gi = b * 256 + threadIdx.x;
        if (gi < 4096) {                               // conv1
            int i = gi;
            int s = i & 1, lane = (i >> 1) & 31;
            int cn = i >> 6, nt = cn & 3, c = cn >> 2;
            int t = lane & 3, g = lane >> 2;
            int n = nt * 8 + g;
            int ic = c >> 2, ky = (c & 3) * 2 + s, kx = 2 * t;
            const float* base = c1w + ((n * 4 + ic) * 8 + ky) * 8 + kx;
            w1f[i] = packbf(base[0], base[1]);
        } else if (gi < 20480) {                       // conv2 (chunk = pos*2+h, k = ic)
            int i = gi - 4096;
            int s = i & 1, lane = (i >> 1) & 31;
            int cn = i >> 6, nt = cn & 7, c = cn >> 3;
            int t = lane & 3, g = lane >> 2;
            int n = nt * 8 + g;
            int pos = c >> 1, h = c & 1;
            int ic = h * 16 + s * 8 + 2 * t;
            int ky = pos >> 2, kx = pos & 3;
            const float* base = c2w + ((n * 32 + ic) * 4 + ky) * 4 + kx;
            w2f[i] = packbf(base[0], base[16]);        // ic+1 -> +16 floats
        } else if (gi < 38912) {                       // conv3
            int i = gi - 20480;
            int s = i & 1, lane = (i >> 1) & 31;
            int cn = i >> 6, nt = cn & 7, c = cn >> 3;
            int t = lane & 3, g = lane >> 2;
            int n = nt * 8 + g;
            int p = c >> 2, icc = c & 3;
            int ic = icc * 16 + s * 8 + 2 * t;
            int ky = p / 3, kx = p % 3;
            float lo = c3w[((n * 64 + ic) * 3 + ky) * 3 + kx];
            float hi = c3w[((n * 64 + ic + 1) * 3 + ky) * 3 + kx];
            w3f[i] = packbf(lo, hi);
        } else if (gi < 71680) {                       // e1 (NTg=32)
            int i = gi - 38912;
            int s = i & 1, lane = (i >> 1) & 31;
            int cn = i >> 6, nt = cn & 31, c = cn >> 5;
            int t = lane & 3, g = lane >> 2;
            int n = nt * 8 + g;
            int k0 = c * 16 + s * 8 + 2 * t;
            we1[i] = packbf(e1w[(size_t)k0 * 256 + n], e1w[(size_t)(k0 + 1) * 256 + n]);
        } else if (gi < 79872) {                       // e2 (NTg=8)
            int i = gi - 71680;
            int s = i & 1, lane = (i >> 1) & 31;
            int cn = i >> 6, nt = cn & 7, c = cn >> 3;
            int t = lane & 3, g = lane >> 2;
            int n = nt * 8 + g;
            int k0 = c * 16 + s * 8 + 2 * t;
            we2[i] = packbf(e2w[(size_t)k0 * 64 + n], e2w[(size_t)(k0 + 1) * 64 + n]);
        } else if (gi < 112640) {                      // pw1 (NTg=32)
            int i = gi - 79872;
            int s = i & 1, lane = (i >> 1) & 31;
            int cn = i >> 6, nt = cn & 31, c = cn >> 5;
            int t = lane & 3, g = lane >> 2;
            int n = nt * 8 + g;
            int k0 = c * 16 + s * 8 + 2 * t;
            wp1[i] = packbf(pw1[(size_t)k0 * 256 + n], pw1[(size_t)(k0 + 1) * 256 + n]);
        }
    } else {
        const int bb = b - 440;
        const int kb = bb * 32;
        for (int j = threadIdx.x; j < 2048; j += 256) {
            int krel = j >> 6, n4 = (j & 63) * 4;
            float4 v = *(const float4*)&fcw[(size_t)(kb + krel) * 256 + n4];
            float* row = S + krel * 257 + n4;
            row[0] = v.x; row[1] = v.y; row[2] = v.z; row[3] = v.w;
        }
        __syncthreads();
        for (int j = threadIdx.x; j < 4096; j += 256) {
            int s = j & 1, lane = (j >> 1) & 31;
            int nt = (j >> 6) & 31, cl = j >> 11;
            int t = lane & 3, g = lane >> 2;
            int krel = cl * 16 + s * 8 + 2 * t;
            int n = nt * 8 + g;
            wfc[((size_t)(2 * bb + cl) * 32 + nt) * 64 + lane * 2 + s] =
                packbf(S[krel * 257 + n], S[(krel + 1) * 257 + n]);
        }
    }
}

// ---------------------------------------------------------------------------
// conv1: grid (512 pairs, 5 oy-groups), 160 thr. Scalar A (smem) + gmem B.
// NHWC output: a1[img][pix][oc] with paired-oc u32 stores.
// ---------------------------------------------------------------------------
__global__ void __launch_bounds__(160, 7)
conv1_mma(const float* __restrict__ curr,
          const float* __restrict__ next,
          const u32* __restrict__ wfu,
          const float* __restrict__ bias,
          __nv_bfloat16* __restrict__ out) {
    extern __shared__ char smc[];
    __nv_bfloat16* simg = (__nv_bfloat16*)smc;     // 2*6720 bf16
    const int p = blockIdx.x, oyg = blockIdx.y;
    const int iy0 = oyg * 16;
    const float* in0 = curr + (size_t)p * 28224;
    const float* in1 = next + (size_t)p * 28224;
    for (int i = threadIdx.x; i < 3360; i += 160) {
        int e = i * 4;
        int im = e / 6720, e2 = e % 6720;
        int ic = e2 / 1680, rem = e2 % 1680;
        const float* src = im ? in1 : in0;
        float4 v = *(const float4*)&src[ic * 7056 + iy0 * 84 + rem];
        u32* d = (u32*)&simg[e];
        d[0] = packbf(v.x, v.y);
        d[1] = packbf(v.z, v.w);
    }
    __syncthreads();

    const int lane = threadIdx.x & 31, wid = threadIdx.x >> 5;
    const int t = lane & 3;
    const int r0 = wid * 16 + (lane >> 2), r1 = r0 + 8;
    const int b00 = (r0 / 20) * 336 + (r0 % 20) * 4 + 2 * t;
    const int b01 = (r1 / 20) * 336 + (r1 % 20) * 4 + 2 * t;
    const u32* wlane = wfu + lane * 2;

    float acc[2][4][4];
    #pragma unroll
    for (int nt = 0; nt < 4; nt++) {
        int oc = nt * 8 + t * 2;
        float b0 = bias[oc], b1 = bias[oc + 1];
        #pragma unroll
        for (int im = 0; im < 2; im++) {
            acc[im][nt][0] = b0; acc[im][nt][1] = b1;
            acc[im][nt][2] = b0; acc[im][nt][3] = b1;
        }
    }
    u32 a0[4], a1[4];
    uint2 bv[4];
    a0[0] = *(const u32*)&simg[b00];
    a0[1] = *(const u32*)&simg[b01];
    a0[2] = *(const u32*)&simg[84 + b00];
    a0[3] = *(const u32*)&simg[84 + b01];
    a1[0] = *(const u32*)&simg[6720 + b00];
    a1[1] = *(const u32*)&simg[6720 + b01];
    a1[2] = *(const u32*)&simg[6720 + 84 + b00];
    a1[3] = *(const u32*)&simg[6720 + 84 + b01];
    #pragma unroll
    for (int nt = 0; nt < 4; nt++)
        bv[nt] = *(const uint2*)&wlane[nt * 64];

    #pragma unroll
    for (int c = 0; c < 16; c++) {
        u32 na0[4], na1[4];
        uint2 nbv[4];
        if (c < 15) {
            const int o = ((c + 1) >> 2) * 1680 + ((c + 1) & 3) * 168;
            na0[0] = *(const u32*)&simg[o + b00];
            na0[1] = *(const u32*)&simg[o + b01];
            na0[2] = *(const u32*)&simg[o + 84 + b00];
            na0[3] = *(const u32*)&simg[o + 84 + b01];
            na1[0] = *(const u32*)&simg[6720 + o + b00];
            na1[1] = *(const u32*)&simg[6720 + o + b01];
            na1[2] = *(const u32*)&simg[6720 + o + 84 + b00];
            na1[3] = *(const u32*)&simg[6720 + o + 84 + b01];
            #pragma unroll
            for (int nt = 0; nt < 4; nt++)
                nbv[nt] = *(const uint2*)&wlane[((c + 1) * 4 + nt) * 64];
        }
        #pragma unroll
        for (int nt = 0; nt < 4; nt++) {
            u32 b[2] = {bv[nt].x, bv[nt].y};
            mmabf(acc[0][nt], a0, b);
            mmabf(acc[1][nt], a1, b);
        }
        if (c < 15) {
            #pragma unroll
            for (int q = 0; q < 4; q++) { a0[q] = na0[q]; a1[q] = na1[q]; }
            #pragma unroll
            for (int nt = 0; nt < 4; nt++) bv[nt] = nbv[nt];
        }
    }
    #pragma unroll
    for (int im = 0; im < 2; im++) {
        const int img = p + im * 512;
        __nv_bfloat16* ob = out + (size_t)img * 12800 + (size_t)(oyg * 80) * 32;
        #pragma unroll
        for (int nt = 0; nt < 4; nt++) {
            int oc = nt * 8 + t * 2;
            *(u32*)&ob[r0 * 32 + oc] =
                packbf(fmaxf(acc[im][nt][0], 0.0f), fmaxf(acc[im][nt][1], 0.0f));
            *(u32*)&ob[r1 * 32 + oc] =
                packbf(fmaxf(acc[im][nt][2], 0.0f), fmaxf(acc[im][nt][3], 0.0f));
        }
    }
}

// ---------------------------------------------------------------------------
// conv2: grid (512 pairs, 2 oc-halves), 192 thr (6 warps, M=32/warp).
// NHWC input; A via LDSM (ic contiguous) + gmem B. cp.async staging.
// chunk c = pos*2 + h (pos = ky*4+kx), k = ic.
// ---------------------------------------------------------------------------
__global__ void __launch_bounds__(192, 4)
conv2_mma(const __nv_bfloat16* __restrict__ a1,
          const u32* __restrict__ wfu,
          const float* __restrict__ bias,
          __nv_bfloat16* __restrict__ out) {
    extern __shared__ char smc[];
    const int p = blockIdx.x, q = blockIdx.y;
    const uint4* src = (const uint4*)(a1 + (size_t)p * 25600);
    const u32 sb0 = smem_u32(smc);
    for (int i = threadIdx.x; i < 3200; i += 192)
        cpa16(sb0 + (u32)i * 16u, &src[i]);
    cpa_commit();
    cpa_wait<0>();
    __syncthreads();

    const int lane = threadIdx.x & 31, wid = threadIdx.x >> 5;
    const int t = lane & 3;
    const int rb = wid * 32 + (lane >> 2);
    int rr[4] = {rb, rb + 8, rb + 16, rb + 24};
    int IM[4], PX[4];
    #pragma unroll
    for (int k = 0; k < 4; k++) {
        int gg = (rr[k] < 162) ? rr[k] : 161;
        IM[k] = gg / 81; PX[k] = gg % 81;
    }
    // ldmatrix lane base addresses for the two 16-row groups
    u32 laG[2];
    #pragma unroll
    for (int G = 0; G < 2; G++) {
        int rL = wid * 32 + G * 16 + (lane & 15);
        if (rL > 161) rL = 161;
        int imL = rL / 81, pxL = rL % 81;
        int oy = pxL / 9, ox = pxL % 9;
        laG[G] = sb0 + (u32)(imL * 25600 + (oy * 40 + ox * 2) * 64)
                     + ((lane & 16) ? 16u : 0u);
    }
    const u32* wlane = wfu + (size_t)q * 4 * 64 + lane * 2;

    float acc[2][4][4];
    #pragma unroll
    for (int nt = 0; nt < 4; nt++) {
        int oc = q * 32 + nt * 8 + t * 2;
        float b0 = bias[oc], b1 = bias[oc + 1];
        #pragma unroll
        for (int G = 0; G < 2; G++) {
            acc[G][nt][0] = b0; acc[G][nt][1] = b1;
            acc[G][nt][2] = b0; acc[G][nt][3] = b1;
        }
    }

    u32 aG0[4], aG1[4];
    uint2 bv[4];
    ldsm4(aG0, laG[0]);
    ldsm4(aG1, laG[1]);
    #pragma unroll
    for (int nt = 0; nt < 4; nt++)
        bv[nt] = *(const uint2*)&wlane[nt * 64];

    #pragma unroll
    for (int c = 0; c < 32; c++) {
        u32 na0[4], na1[4];
        uint2 nbv[4];
        if (c < 31) {
            const int cc = c + 1;
            const int pos = cc >> 1, h = cc & 1;
            const u32 off = (u32)(((pos >> 2) * 20 + (pos & 3)) * 64 + h * 32);
            ldsm4(na0, laG[0] + off);
            ldsm4(na1, laG[1] + off);
            #pragma unroll
            for (int nt = 0; nt < 4; nt++)
                nbv[nt] = *(const uint2*)&wlane[(cc * 8 + nt) * 64];
        }
        #pragma unroll
        for (int nt = 0; nt < 4; nt++) {
            u32 b[2] = {bv[nt].x, bv[nt].y};
            mmabf(acc[0][nt], aG0, b);
            mmabf(acc[1][nt], aG1, b);
        }
        if (c < 31) {
            #pragma unroll
            for (int k = 0; k < 4; k++) { aG0[k] = na0[k]; aG1[k] = na1[k]; }
            #pragma unroll
            for (int nt = 0; nt < 4; nt++) bv[nt] = nbv[nt];
        }
    }
    #pragma unroll
    for (int G = 0; G < 2; G++) {
        #pragma unroll
        for (int nt = 0; nt < 4; nt++) {
            int oc = q * 32 + nt * 8 + t * 2;
            const int k0 = G * 2, k1 = G * 2 + 1;
            if (rr[k0] < 162)
                *(u32*)&out[((size_t)(p * 2 + IM[k0]) * 81 + PX[k0]) * 64 + oc] =
                    packbf(fmaxf(acc[G][nt][0], 0.0f), fmaxf(acc[G][nt][1], 0.0f));
            if (rr[k1] < 162)
                *(u32*)&out[((size_t)(p * 2 + IM[k1]) * 81 + PX[k1]) * 64 + oc] =
                    packbf(fmaxf(acc[G][nt][2], 0.0f), fmaxf(acc[G][nt][3], 0.0f));
        }
    }
}

// ---------------------------------------------------------------------------
// conv3: grid (512, 2 oc-halves), 128 thr (4 warps, M=32/warp).
// LDSM A x2 groups sharing gmem-B frags. 5 blocks/SM.
// ---------------------------------------------------------------------------
__global__ void __launch_bounds__(128, 5)
conv3_mma(const __nv_bfloat16* __restrict__ a2n,
          const u32* __restrict__ wfu,
          const float* __restrict__ bias,
          __nv_bfloat16* __restrict__ feat) {
    extern __shared__ char smc[];
    __nv_bfloat16* sin = (__nv_bfloat16*)smc;      // 2*81*72 bf16
    const int q = blockIdx.y;
    const int imgb = blockIdx.x * 2;
    for (int i = threadIdx.x; i < 1296; i += 128) {
        int im = i / 648, r = i % 648;
        int px = r >> 3, qq = r & 7;
        *((uint4*)&sin[im * 5832 + px * 72]       + qq) =
        *((const uint4*)&a2n[((size_t)(imgb + im) * 81 + px) * 64] + qq);
    }
    __syncthreads();

    const int lane = threadIdx.x & 31, wid = threadIdx.x >> 5;
    const int t = lane & 3;
    const u32 sb = smem_u32(smc);
    u32 laG[2];
    #pragma unroll
    for (int G = 0; G < 2; G++) {
        int r = wid * 32 + G * 16 + (lane & 15);
        if (r > 97) r = 97;
        int im = r / 49, lp = r % 49;
        laG[G] = sb + (u32)(im * 11664 + ((lp / 7) * 9 + lp % 7) * 144)
                    + ((lane & 16) ? 16u : 0u);
    }
    const u32* wlane = wfu + (size_t)q * 4 * 64 + lane * 2;

    float acc[2][4][4];
    #pragma unroll
    for (int nt = 0; nt < 4; nt++) {
        int oc = q * 32 + nt * 8 + t * 2;
        float b0 = bias[oc], b1 = bias[oc + 1];
        #pragma unroll
        for (int G = 0; G < 2; G++) {
            acc[G][nt][0] = b0; acc[G][nt][1] = b1;
            acc[G][nt][2] = b0; acc[G][nt][3] = b1;
        }
    }

    u32 a0[4], a1[4];
    uint2 bv[4];
    ldsm4(a0, laG[0]);
    ldsm4(a1, laG[1]);
    #pragma unroll
    for (int nt = 0; nt < 4; nt++)
        bv[nt] = *(const uint2*)&wlane[nt * 64];

    #pragma unroll
    for (int c = 0; c < 36; c++) {
        u32 na0[4], na1[4];
        uint2 nbv[4];
        if (c < 35) {
            const int pp = (c + 1) >> 2, icc = (c + 1) & 3;
            const u32 off = (u32)(((pp / 3) * 9 + (pp % 3)) * 144 + icc * 32);
            ldsm4(na0, laG[0] + off);
            ldsm4(na1, laG[1] + off);
            #pragma unroll
            for (int nt = 0; nt < 4; nt++)
                nbv[nt] = *(const uint2*)&wlane[((c + 1) * 8 + nt) * 64];
        }
        #pragma unroll
        for (int nt = 0; nt < 4; nt++) {
            u32 b[2] = {bv[nt].x, bv[nt].y};
            mmabf(acc[0][nt], a0, b);
            mmabf(acc[1][nt], a1, b);
        }
        if (c < 35) {
            #pragma unroll
            for (int k = 0; k < 4; k++) { a0[k] = na0[k]; a1[k] = na1[k]; }
            #pragma unroll
            for (int nt = 0; nt < 4; nt++) bv[nt] = nbv[nt];
        }
    }
    #pragma unroll
    for (int G = 0; G < 2; G++) {
        const int r0 = wid * 32 + G * 16 + (lane >> 2), r1 = r0 + 8;
        const int g0 = (r0 < 98) ? r0 : 97, g1 = (r1 < 98) ? r1 : 97;
        const int im0 = g0 / 49, lp0 = g0 % 49;
        const int im1 = g1 / 49, lp1 = g1 % 49;
        #pragma unroll
        for (int nt = 0; nt < 4; nt++) {
            int oc = q * 32 + nt * 8 + t * 2;
            if (r0 < 98) {
                __nv_bfloat16* fb = feat + (size_t)(imgb + im0) * 3136 + oc * 49 + lp0;
                fb[0]  = __float2bfloat16(fmaxf(acc[G][nt][0], 0.0f));
                fb[49] = __float2bfloat16(fmaxf(acc[G][nt][1], 0.0f));
            }
            if (r1 < 98) {
                __nv_bfloat16* fb = feat + (size_t)(imgb + im1) * 3136 + oc * 49 + lp1;
                fb[0]  = __float2bfloat16(fmaxf(acc[G][nt][2], 0.0f));
                fb[49] = __float2bfloat16(fmaxf(acc[G][nt][3], 0.0f));
            }
        }
    }
}

// ---------------------------------------------------------------------------
// FC (bf16 mma): [1024,3136]@[3136,256], split-K 4, cp.async double-buffered.
// ---------------------------------------------------------------------------
__global__ void fc_mma(const __nv_bfloat16* __restrict__ feat,
                       const u32* __restrict__ wfu,
                       float* __restrict__ part) {
    extern __shared__ char smc[];
    const int mb = blockIdx.x, nb = blockIdx.y, z = blockIdx.z;
    const int m0b = mb * 128;
    const int lane = threadIdx.x & 31, wid = threadIdx.x >> 5;
    const int t = lane & 3, g = lane >> 2;
    const u32 sbase = smem_u32(smc);

    #define FC_STAGE(IT, BUF) do {                                            \
        const int kbase_ = z * 784 + (IT) * 112;                              \
        const int cbase_ = z * 49 + (IT) * 7;                                 \
        const u32 aoff_ = sbase + (BUF) * 30720u;                             \
        for (int i = threadIdx.x; i < 1792; i += 256) {                       \
            int row_ = i / 14, seg_ = i % 14;                                 \
            cpa16(aoff_ + (u32)(row_ * 120 + seg_ * 8) * 2u,                  \
                  &feat[(size_t)(m0b + row_) * 3136 + kbase_ + seg_ * 8]);    \
        }                                                                     \
        const u32 boff_ = sbase + 61440u + (BUF) * 14336u;                    \
        for (int i = threadIdx.x; i < 896; i += 256) {                        \
            int cn_ = i >> 4, cl_ = cn_ >> 3, ntl_ = cn_ & 7;                 \
            cpa16(boff_ + (u32)i * 16u,                                       \
                  &wfu[((size_t)(cbase_ + cl_) * 32 + nb * 8 + ntl_) * 64     \
                       + (i & 15) * 4]);                                      \
        }                                                                     \
    } while (0)

    float acc[8][4] = {};
    FC_STAGE(0, 0);
    cpa_commit();
    for (int it = 0; it < 7; it++) {
        if (it < 6) {
            FC_STAGE(it + 1, (it + 1) & 1);
            cpa_commit();
            cpa_wait<1>();
        } else {
            cpa_wait<0>();
        }
        __syncthreads();
        const __nv_bfloat16* sA = (const __nv_bfloat16*)(smc + (it & 1) * 30720);
        const u32* sB = (const u32*)(smc + 61440 + (it & 1) * 14336);
        #pragma unroll
        for (int c_l = 0; c_l < 7; c_l++) {
            const int ra = (wid * 16 + g) * 120 + c_l * 16 + 2 * t;
            u32 a[4];
            a[0] = *(const u32*)&sA[ra];
            a[1] = *(const u32*)&sA[ra + 8 * 120];
            a[2] = *(const u32*)&sA[ra + 8];
            a[3] = *(const u32*)&sA[ra + 8 * 120 + 8];
            const u32* wb = sB + c_l * 512 + lane * 2;
            #pragma unroll
            for (int nt = 0; nt < 8; nt++) {
                uint2 bv = *(const uint2*)&wb[nt * 64];
                u32 b[2] = {bv.x, bv.y};
                mmabf(acc[nt], a, b);
            }
        }
        __syncthreads();
    }
    #undef FC_STAGE

    float* pb = part + (size_t)z * 262144;
    const int mr0 = m0b + wid * 16 + g, mr1 = mr0 + 8;
    #pragma unroll
    for (int nt = 0; nt < 8; nt++) {
        int col = nb * 64 + nt * 8 + 2 * t;
        *(float2*)&pb[(size_t)mr0 * 256 + col] = make_float2(acc[nt][0], acc[nt][1]);
        *(float2*)&pb[(size_t)mr1 * 256 + col] = make_float2(acc[nt][2], acc[nt][3]);
    }
}

// ---------------------------------------------------------------------------
// head GEMM bodies
// ---------------------------------------------------------------------------
__device__ void head_bodyP(const float* __restrict__ part, int rowOff,
                           const float* __restrict__ fcb,
                           const u32* __restrict__ wfu,
                           const float* __restrict__ bias,
                           float* __restrict__ C,
                           int NTg, int mb, int nb) {
    extern __shared__ char smc[];
    __nv_bfloat16* sA = (__nv_bfloat16*)smc;
    u32* sB = (u32*)(smc + 34816);
    const int m0b = mb * 128;
    const int N = NTg * 8;
    const int lane = threadIdx.x & 31, wid = threadIdx.x >> 5;
    const int t = lane & 3, g = lane >> 2;

    float acc[8][4] = {};
    #pragma unroll
    for (int it = 0; it < 2; it++) {
        const int kbase = it * 128;
        __syncthreads();
        for (int i = threadIdx.x; i < 4096; i += 256) {
            int row = i >> 5, seg = i & 31;
            size_t idx = (size_t)(rowOff + m0b + row) * 256 + kbase + seg * 4;
            float4 v = *(const float4*)&fcb[kbase + seg * 4];
            float4 p0 = *(const float4*)&part[idx];
            float4 p1 = *(const float4*)&part[262144 + idx];
            float4 p2 = *(const float4*)&part[524288 + idx];
            float4 p3 = *(const float4*)&part[786432 + idx];
            v.x = fmaxf(v.x + p0.x + p1.x + p2.x + p3.x, 0.0f);
            v.y = fmaxf(v.y + p0.y + p1.y + p2.y + p3.y, 0.0f);
            v.z = fmaxf(v.z + p0.z + p1.z + p2.z + p3.z, 0.0f);
            v.w = fmaxf(v.w + p0.w + p1.w + p2.w + p3.w, 0.0f);
            u32* d = (u32*)&sA[row * 136 + seg * 4];
            d[0] = packbf(v.x, v.y);
            d[1] = packbf(v.z, v.w);
        }
        for (int i = threadIdx.x; i < 1024; i += 256) {
            int cn = i >> 4, c_l = cn >> 3, ntl = cn & 7;
            ((uint4*)sB)[i] =
                *(const uint4*)&wfu[(((it * 8 + c_l) * NTg) + nb * 8 + ntl) * 64 + (i & 15) * 4];
        }
        __syncthreads();
        #pragma unroll
        for (int c_l = 0; c_l < 8; c_l++) {
            const int ra = (wid * 16 + g) * 136 + c_l * 16 + 2 * t;
            u32 a[4];
            a[0] = *(const u32*)&sA[ra];
            a[1] = *(const u32*)&sA[ra + 8 * 136];
            a[2] = *(const u32*)&sA[ra + 8];
            a[3] = *(const u32*)&sA[ra + 8 * 136 + 8];
            const u32* wb = sB + c_l * 512 + lane * 2;
            #pragma unroll
            for (int nt = 0; nt < 8; nt++) {
                uint2 bv = *(const uint2*)&wb[nt * 64];
                u32 b[2] = {bv.x, bv.y};
                mmabf(acc[nt], a, b);
            }
        }
    }
    const int mr0 = m0b + wid * 16 + g, mr1 = mr0 + 8;
    #pragma unroll
    for (int nt = 0; nt < 8; nt++) {
        int col = nb * 64 + nt * 8 + 2 * t;
        float b0 = bias[col], b1 = bias[col + 1];
        float v00 = fmaxf(acc[nt][0] + b0, 0.0f), v01 = fmaxf(acc[nt][1] + b1, 0.0f);
        float v10 = fmaxf(acc[nt][2] + b0, 0.0f), v11 = fmaxf(acc[nt][3] + b1, 0.0f);
        *(float2*)&C[(size_t)mr0 * N + col] = make_float2(v00, v01);
        *(float2*)&C[(size_t)mr1 * N + col] = make_float2(v10, v11);
    }
}

__device__ void head_body(const float* __restrict__ A,
                          const u32* __restrict__ wfu,
                          const float* __restrict__ bias,
                          float* __restrict__ C,
                          int NTg, int doRelu, int mb, int nb) {
    extern __shared__ char smc[];
    __nv_bfloat16* sA = (__nv_bfloat16*)smc;
    u32* sB = (u32*)(smc + 34816);
    const int m0b = mb * 128;
    const int N = NTg * 8;
    const int lane = threadIdx.x & 31, wid = threadIdx.x >> 5;
    const int t = lane & 3, g = lane >> 2;

    float acc[8][4] = {};
    #pragma unroll
    for (int it = 0; it < 2; it++) {
        const int kbase = it * 128;
        __syncthreads();
        for (int i = threadIdx.x; i < 4096; i += 256) {
            int row = i >> 5, seg = i & 31;
            float4 v = *(const float4*)&A[(size_t)(m0b + row) * 256 + kbase + seg * 4];
            u32* d = (u32*)&sA[row * 136 + seg * 4];
            d[0] = packbf(v.x, v.y);
            d[1] = packbf(v.z, v.w);
        }
        for (int i = threadIdx.x; i < 1024; i += 256) {
            int cn = i >> 4, c_l = cn >> 3, ntl = cn & 7;
            ((uint4*)sB)[i] =
                *(const uint4*)&wfu[(((it * 8 + c_l) * NTg) + nb * 8 + ntl) * 64 + (i & 15) * 4];
        }
        __syncthreads();
        #pragma unroll
        for (int c_l = 0; c_l < 8; c_l++) {
            const int ra = (wid * 16 + g) * 136 + c_l * 16 + 2 * t;
            u32 a[4];
            a[0] = *(const u32*)&sA[ra];
            a[1] = *(const u32*)&sA[ra + 8 * 136];
            a[2] = *(const u32*)&sA[ra + 8];
            a[3] = *(const u32*)&sA[ra + 8 * 136 + 8];
            const u32* wb = sB + c_l * 512 + lane * 2;
            #pragma unroll
            for (int nt = 0; nt < 8; nt++) {
                uint2 bv = *(const uint2*)&wb[nt * 64];
                u32 b[2] = {bv.x, bv.y};
                mmabf(acc[nt], a, b);
            }
        }
    }
    const int mr0 = m0b + wid * 16 + g, mr1 = mr0 + 8;
    #pragma unroll
    for (int nt = 0; nt < 8; nt++) {
        int col = nb * 64 + nt * 8 + 2 * t;
        float b0 = bias[col], b1 = bias[col + 1];
        float v00 = acc[nt][0] + b0, v01 = acc[nt][1] + b1;
        float v10 = acc[nt][2] + b0, v11 = acc[nt][3] + b1;
        if (doRelu) {
            v00 = fmaxf(v00, 0.0f); v01 = fmaxf(v01, 0.0f);
            v10 = fmaxf(v10, 0.0f); v11 = fmaxf(v11, 0.0f);
        }
        *(float2*)&C[(size_t)mr0 * N + col] = make_float2(v00, v01);
        *(float2*)&C[(size_t)mr1 * N + col] = make_float2(v10, v11);
    }
}

__global__ void headA(const float* __restrict__ part, const float* __restrict__ fcb,
                      const u32* __restrict__ we1, const float* __restrict__ e1b,
                      float* __restrict__ h1,
                      const u32* __restrict__ wp1, const float* __restrict__ pb1,
                      float* __restrict__ hp) {
    int bid = blockIdx.x;
    if (bid < 32) head_bodyP(part, 0, fcb, we1, e1b, h1, 32, bid >> 2, bid & 3);
    else {
        bid -= 32;
        head_bodyP(part, 512, fcb, wp1, pb1, hp, 32, bid >> 2, bid & 3);
    }
}

__global__ void headB(const float* __restrict__ h1,
                      const u32* __restrict__ we2, const float* __restrict__ e2b,
                      float* __restrict__ phi,
                      const float* __restrict__ hp,
                      const float* __restrict__ pw2, const float* __restrict__ pb2,
                      float* __restrict__ cy) {
    int bid = blockIdx.x;
    if (bid < 8) {
        head_body(h1, we2, e2b, phi, 8, 0, bid, 0);
    } else {
        const int gw = (bid - 8) * 8 + (threadIdx.x >> 5);
        const int lane = threadIdx.x & 31;
        float s = 0.0f;
        for (int k = lane; k < 256; k += 32)
            s = fmaf(hp[(size_t)gw * 256 + k], pw2[k], s);
        #pragma unroll
        for (int off = 16; off > 0; off >>= 1) s += __shfl_xor_sync(0xffffffffu, s, off);
        if (lane == 0) cy[gw] = s + pb2[0];
    }
}

// ---------------------------------------------------------------------------
// logits: 4 rows/block (grid 128), float4 y loads + fused final loss.
// ---------------------------------------------------------------------------
__global__ void logits_kernel(const float* __restrict__ phi,
                              const float* __restrict__ cy,
                              float* __restrict__ lse,
                              float* __restrict__ diag,
                              float* __restrict__ out) {
    const int i0 = blockIdx.x * 4;
    __shared__ float sx[4][64];
    __shared__ float red[256];
    __shared__ float red2[256];
    __shared__ float sdiag[4];
    __shared__ int isLast;
    const int tid = threadIdx.x;
    sx[tid >> 6][tid & 63] = phi[(size_t)(i0 + (tid >> 6)) * 64 + (tid & 63)];
    __syncthreads();

    float lg[2][4];
    #pragma unroll
    for (int rep = 0; rep < 2; rep++) {
        const int j = tid + rep * 256;
        const float4* y4 = (const float4*)(phi + (size_t)(512 + j) * 64);
        float mx[4] = {0.f, 0.f, 0.f, 0.f}, ss[4] = {0.f, 0.f, 0.f, 0.f};
        #pragma unroll
        for (int k4 = 0; k4 < 8; k4++) {
            const float4 v = y4[k4];
            #pragma unroll
            for (int r = 0; r < 4; r++) {
                float d0 = sx[r][k4 * 4 + 0] - v.x;
                float d1 = sx[r][k4 * 4 + 1] - v.y;
                float d2 = sx[r][k4 * 4 + 2] - v.z;
                float d3 = sx[r][k4 * 4 + 3] - v.w;
                mx[r] = fmaxf(mx[r], fmaxf(fmaxf(d0, d1), fmaxf(d2, d3)));
            }
        }
        #pragma unroll
        for (int k4 = 8; k4 < 16; k4++) {
            const float4 v = y4[k4];
            #pragma unroll
            for (int r = 0; r < 4; r++) {
                float d0 = sx[r][k4 * 4 + 0] - v.x;
                float d1 = sx[r][k4 * 4 + 1] - v.y;
                float d2 = sx[r][k4 * 4 + 2] - v.z;
                float d3 = sx[r][k4 * 4 + 3] - v.w;
                ss[r] = fmaf(d0, d0, ss[r]);
                ss[r] = fmaf(d1, d1, ss[r]);
                ss[r] = fmaf(d2, d2, ss[r]);
                ss[r] = fmaf(d3, d3, ss[r]);
            }
        }
        const float cyj = cy[j];
        #pragma unroll
        for (int r = 0; r < 4; r++) {
            lg[rep][r] = cyj - (mx[r] + sqrtf(ss[r] + 1e-8f));
            if (j == i0 + r) sdiag[r] = lg[rep][r];
        }
    }
    #pragma unroll
    for (int r = 0; r < 4; r++) {
        __syncthreads();
        red[tid] = fmaxf(lg[0][r], lg[1][r]);
        __syncthreads();
        for (int s = 128; s > 0; s >>= 1) {
            if (tid < s) red[tid] = fmaxf(red[tid], red[tid + s]);
            __syncthreads();
        }
        const float rowmax = red[0];
        __syncthreads();
        red[tid] = expf(lg[0][r] - rowmax) + expf(lg[1][r] - rowmax);
        __syncthreads();
        for (int s = 128; s > 0; s >>= 1) {
            if (tid < s) red[tid] += red[tid + s];
            __syncthreads();
        }
        if (tid == 0) {
            lse[i0 + r] = rowmax + logf(red[0]);
            diag[i0 + r] = sdiag[r];
        }
    }

    __threadfence();
    if (tid == 0) isLast = (atomicAdd(&g_done, 1) == 127) ? 1 : 0;
    __syncthreads();
    if (isLast) {
        __threadfence();
        float s1 = 0.0f, s2 = 0.0f;
        for (int i = tid; i < 512; i += 256) {
            const float l = lse[i];
            s1 += l - diag[i];
            const float u = l + 1e-6f;
            s2 = fmaf(u, u, s2);
        }
        red[tid] = s1; red2[tid] = s2;
        __syncthreads();
        for (int s = 128; s > 0; s >>= 1) {
            if (tid < s) { red[tid] += red[tid + s]; red2[tid] += red2[tid + s]; }
            __syncthreads();
        }
        if (tid == 0) {
            out[0] = red[0] * (1.0f / 512.0f) + 0.1f * red2[0] * (1.0f / 512.0f);
            g_done = 0;
        }
    }
}

// ---------------------------------------------------------------------------
// Host launcher
// ---------------------------------------------------------------------------
extern "C" void kernel_launch(void* const* d_in, const int* in_sizes, int n_in,
                              void* d_out, int out_size) {
    const float* curr = (const float*)d_in[0];
    const float* next = (const float*)d_in[1];
    const float* c1w = (const float*)d_in[2];
    const float* c1b = (const float*)d_in[3];
    const float* c2w = (const float*)d_in[4];
    const float* c2b = (const float*)d_in[5];
    const float* c3w = (const float*)d_in[6];
    const float* c3b = (const float*)d_in[7];
    const float* fcw = (const float*)d_in[8];
    const float* fcb = (const float*)d_in[9];
    const float* e1w = (const float*)d_in[10];
    const float* e1b = (const float*)d_in[11];
    const float* e2w = (const float*)d_in[12];
    const float* e2b = (const float*)d_in[13];
    const float* pw1 = (const float*)d_in[14];
    const float* pb1 = (const float*)d_in[15];
    const float* pw2 = (const float*)d_in[16];
    const float* pb2 = (const float*)d_in[17];

    u32 *p_w1f, *p_w2f, *p_w3f, *p_wfc, *p_we1, *p_we2, *p_wp1;
    __nv_bfloat16 *p_a1, *p_a2n, *p_feat;
    float *p_h1, *p_phi, *p_hp, *p_cy, *p_lse, *p_diag, *p_part;
    cudaGetSymbolAddress((void**)&p_w1f, g_w1f);
    cudaGetSymbolAddress((void**)&p_w2f, g_w2f);
    cudaGetSymbolAddress((void**)&p_w3f, g_w3f);
    cudaGetSymbolAddress((void**)&p_wfc, g_wfc);
    cudaGetSymbolAddress((void**)&p_we1, g_we1);
    cudaGetSymbolAddress((void**)&p_we2, g_we2);
    cudaGetSymbolAddress((void**)&p_wp1, g_wp1);
    cudaGetSymbolAddress((void**)&p_a1, g_a1);
    cudaGetSymbolAddress((void**)&p_a2n, g_a2n);
    cudaGetSymbolAddress((void**)&p_feat, g_feat);
    cudaGetSymbolAddress((void**)&p_h1, g_h1);
    cudaGetSymbolAddress((void**)&p_phi, g_phi);
    cudaGetSymbolAddress((void**)&p_hp, g_hp);
    cudaGetSymbolAddress((void**)&p_cy, g_cy);
    cudaGetSymbolAddress((void**)&p_lse, g_lse);
    cudaGetSymbolAddress((void**)&p_diag, g_diag);
    cudaGetSymbolAddress((void**)&p_part, g_part);

    const int SM1 = 26880;
    const int SM2 = 51200;
    const int SM3 = 23328;
    const int SMF = 90112;
    const int SMH = 34816 + 4096 * 4;
    cudaFuncSetAttribute(conv1_mma, cudaFuncAttributeMaxDynamicSharedMemorySize, SM1);
    cudaFuncSetAttribute(conv2_mma, cudaFuncAttributeMaxDynamicSharedMemorySize, SM2);
    cudaFuncSetAttribute(conv3_mma, cudaFuncAttributeMaxDynamicSharedMemorySize, SM3);
    cudaFuncSetAttribute(fc_mma, cudaFuncAttributeMaxDynamicSharedMemorySize, SMF);
    cudaFuncSetAttribute(headA, cudaFuncAttributeMaxDynamicSharedMemorySize, SMH);
    cudaFuncSetAttribute(headB, cudaFuncAttributeMaxDynamicSharedMemorySize, SMH);

    prep_all<<<538, 256>>>(c1w, c2w, c3w, fcw, e1w, e2w, pw1,
                           p_w1f, p_w2f, p_w3f, p_wfc, p_we1, p_we2, p_wp1);

    conv1_mma<<<dim3(512, 5), 160, SM1>>>(curr, next, p_w1f, c1b, p_a1);
    conv2_mma<<<dim3(512, 2), 192, SM2>>>(p_a1, p_w2f, c2b, p_a2n);
    conv3_mma<<<dim3(512, 2), 128, SM3>>>(p_a2n, p_w3f, c3b, p_feat);

    fc_mma<<<dim3(8, 4, 4), 256, SMF>>>(p_feat, p_wfc, p_part);

    headA<<<48, 256, SMH>>>(p_part, fcb, p_we1, e1b, p_h1, p_wp1, pb1, p_hp);
    headB<<<72, 256, SMH>>>(p_h1, p_we2, e2b, p_phi, p_hp, pw2, pb2, p_cy);

    logits_kernel<<<128, 256>>>(p_phi, p_cy, p_lse, p_diag, (float*)d_out);
}

// round 17
// speedup vs baseline: 1.1489x; 1.1489x over previous
#include <cuda_runtime.h>
#include <cuda_bf16.h>
#include <math.h>

#define NIMG 1024
typedef unsigned int u32;

// ---------------------------------------------------------------------------
// scratch
// ---------------------------------------------------------------------------
__device__ __align__(128) u32 g_w1f[16 * 4 * 64];
__device__ __align__(128) u32 g_w2f[32 * 8 * 64];
__device__ __align__(128) u32 g_w3f[36 * 8 * 64];
__device__ __align__(128) u32 g_wfc[196 * 32 * 64];
__device__ __align__(128) u32 g_we1[16 * 32 * 64];
__device__ __align__(128) u32 g_we2[16 * 8 * 64];
__device__ __align__(128) u32 g_wp1[16 * 32 * 64];
__device__ __align__(128) __nv_bfloat16 g_a1[(size_t)NIMG * 12800];
__device__ __align__(128) __nv_bfloat16 g_a2n[(size_t)NIMG * 81 * 64];
__device__ __align__(128) __nv_bfloat16 g_feat[(size_t)NIMG * 3136];
__device__ __align__(128) float g_h1[NIMG * 256];
__device__ __align__(128) float g_phi[NIMG * 64];
__device__ __align__(128) float g_hp[512 * 256];
__device__ __align__(128) float g_cy[512];
__device__ __align__(128) float g_lse[512];
__device__ __align__(128) float g_diag[512];
__device__ __align__(128) float g_part[4 * 1024 * 256];
__device__ int g_done = 0;

// ---------------------------------------------------------------------------
// helpers
// ---------------------------------------------------------------------------
__device__ __forceinline__ u32 packbf(float lo, float hi) {
    __nv_bfloat162 h = __float22bfloat162_rn(make_float2(lo, hi));
    return *reinterpret_cast<u32*>(&h);
}
__device__ __forceinline__ void mmabf(float* d, const u32* a, const u32* b) {
    asm volatile(
        "mma.sync.aligned.m16n8k16.row.col.f32.bf16.bf16.f32 "
        "{%0,%1,%2,%3},{%4,%5,%6,%7},{%8,%9},{%0,%1,%2,%3};\n"
        : "+f"(d[0]), "+f"(d[1]), "+f"(d[2]), "+f"(d[3])
        : "r"(a[0]), "r"(a[1]), "r"(a[2]), "r"(a[3]), "r"(b[0]), "r"(b[1]));
}
__device__ __forceinline__ void ldsm4(u32* r, u32 addr) {
    asm volatile("ldmatrix.sync.aligned.m8n8.x4.shared.b16 {%0,%1,%2,%3}, [%4];"
                 : "=r"(r[0]), "=r"(r[1]), "=r"(r[2]), "=r"(r[3]) : "r"(addr));
}
__device__ __forceinline__ u32 smem_u32(const void* p) {
    u32 a;
    asm("{ .reg .u64 t; cvta.to.shared.u64 t, %1; cvt.u32.u64 %0, t; }"
        : "=r"(a) : "l"(p));
    return a;
}
__device__ __forceinline__ void cpa16(u32 saddr, const void* g) {
    asm volatile("cp.async.ca.shared.global [%0], [%1], 16;"
                 :: "r"(saddr), "l"(g));
}
__device__ __forceinline__ void cpa_commit() {
    asm volatile("cp.async.commit_group;");
}
template<int N> __device__ __forceinline__ void cpa_wait() {
    asm volatile("cp.async.wait_group %0;" :: "n"(N));
}

// ---------------------------------------------------------------------------
// unified weight prep (blocks 0..439 scalar, 440..537 tiled fcw)
// ---------------------------------------------------------------------------
__global__ void prep_all(const float* __restrict__ c1w, const float* __restrict__ c2w,
                         const float* __restrict__ c3w, const float* __restrict__ fcw,
                         const float* __restrict__ e1w, const float* __restrict__ e2w,
                         const float* __restrict__ pw1,
                         u32* __restrict__ w1f, u32* __restrict__ w2f,
                         u32* __restrict__ w3f, u32* __restrict__ wfc,
                         u32* __restrict__ we1, u32* __restrict__ we2,
                         u32* __restrict__ wp1) {
    __shared__ float S[32 * 257];
    const int b = blockIdx.x;
    if (b < 440) {
        int gi = b * 256 + threadIdx.x;
        if (gi < 4096) {                               // conv1
            int i = gi;
            int s = i & 1, lane = (i >> 1) & 31;
            int cn = i >> 6, nt = cn & 3, c = cn >> 2;
            int t = lane & 3, g = lane >> 2;
            int n = nt * 8 + g;
            int ic = c >> 2, ky = (c & 3) * 2 + s, kx = 2 * t;
            const float* base = c1w + ((n * 4 + ic) * 8 + ky) * 8 + kx;
            w1f[i] = packbf(base[0], base[1]);
        } else if (gi < 20480) {                       // conv2
            int i = gi - 4096;
            int s = i & 1, lane = (i >> 1) & 31;
            int cn = i >> 6, nt = cn & 7, ic = cn >> 3;
            int t = lane & 3, g = lane >> 2;
            int n = nt * 8 + g;
            int ky = s * 2 + (t >> 1), kx = (t & 1) * 2;
            const float* base = c2w + ((n * 32 + ic) * 4 + ky) * 4 + kx;
            w2f[i] = packbf(base[0], base[1]);
        } else if (gi < 38912) {                       // conv3
            int i = gi - 20480;
            int s = i & 1, lane = (i >> 1) & 31;
            int cn = i >> 6, nt = cn & 7, c = cn >> 3;
            int t = lane & 3, g = lane >> 2;
            int n = nt * 8 + g;
            int p = c >> 2, icc = c & 3;
            int ic = icc * 16 + s * 8 + 2 * t;
            int ky = p / 3, kx = p % 3;
            float lo = c3w[((n * 64 + ic) * 3 + ky) * 3 + kx];
            float hi = c3w[((n * 64 + ic + 1) * 3 + ky) * 3 + kx];
            w3f[i] = packbf(lo, hi);
        } else if (gi < 71680) {                       // e1 (NTg=32)
            int i = gi - 38912;
            int s = i & 1, lane = (i >> 1) & 31;
            int cn = i >> 6, nt = cn & 31, c = cn >> 5;
            int t = lane & 3, g = lane >> 2;
            int n = nt * 8 + g;
            int k0 = c * 16 + s * 8 + 2 * t;
            we1[i] = packbf(e1w[(size_t)k0 * 256 + n], e1w[(size_t)(k0 + 1) * 256 + n]);
        } else if (gi < 79872) {                       // e2 (NTg=8)
            int i = gi - 71680;
            int s = i & 1, lane = (i >> 1) & 31;
            int cn = i >> 6, nt = cn & 7, c = cn >> 3;
            int t = lane & 3, g = lane >> 2;
            int n = nt * 8 + g;
            int k0 = c * 16 + s * 8 + 2 * t;
            we2[i] = packbf(e2w[(size_t)k0 * 64 + n], e2w[(size_t)(k0 + 1) * 64 + n]);
        } else if (gi < 112640) {                      // pw1 (NTg=32)
            int i = gi - 79872;
            int s = i & 1, lane = (i >> 1) & 31;
            int cn = i >> 6, nt = cn & 31, c = cn >> 5;
            int t = lane & 3, g = lane >> 2;
            int n = nt * 8 + g;
            int k0 = c * 16 + s * 8 + 2 * t;
            wp1[i] = packbf(pw1[(size_t)k0 * 256 + n], pw1[(size_t)(k0 + 1) * 256 + n]);
        }
    } else {
        const int bb = b - 440;
        const int kb = bb * 32;
        for (int j = threadIdx.x; j < 2048; j += 256) {
            int krel = j >> 6, n4 = (j & 63) * 4;
            float4 v = *(const float4*)&fcw[(size_t)(kb + krel) * 256 + n4];
            float* row = S + krel * 257 + n4;
            row[0] = v.x; row[1] = v.y; row[2] = v.z; row[3] = v.w;
        }
        __syncthreads();
        for (int j = threadIdx.x; j < 4096; j += 256) {
            int s = j & 1, lane = (j >> 1) & 31;
            int nt = (j >> 6) & 31, cl = j >> 11;
            int t = lane & 3, g = lane >> 2;
            int krel = cl * 16 + s * 8 + 2 * t;
            int n = nt * 8 + g;
            wfc[((size_t)(2 * bb + cl) * 32 + nt) * 64 + lane * 2 + s] =
                packbf(S[krel * 257 + n], S[(krel + 1) * 257 + n]);
        }
    }
}

// ---------------------------------------------------------------------------
// conv1: grid (512 pairs, 5 oy-groups), 160 thr. Scalar A (smem) + gmem B.
// NCHW output.
// ---------------------------------------------------------------------------
__global__ void __launch_bounds__(160, 7)
conv1_mma(const float* __restrict__ curr,
          const float* __restrict__ next,
          const u32* __restrict__ wfu,
          const float* __restrict__ bias,
          __nv_bfloat16* __restrict__ out) {
    extern __shared__ char smc[];
    __nv_bfloat16* simg = (__nv_bfloat16*)smc;     // 2*6720 bf16
    const int p = blockIdx.x, oyg = blockIdx.y;
    const int iy0 = oyg * 16;
    const float* in0 = curr + (size_t)p * 28224;
    const float* in1 = next + (size_t)p * 28224;
    for (int i = threadIdx.x; i < 3360; i += 160) {
        int e = i * 4;
        int im = e / 6720, e2 = e % 6720;
        int ic = e2 / 1680, rem = e2 % 1680;
        const float* src = im ? in1 : in0;
        float4 v = *(const float4*)&src[ic * 7056 + iy0 * 84 + rem];
        u32* d = (u32*)&simg[e];
        d[0] = packbf(v.x, v.y);
        d[1] = packbf(v.z, v.w);
    }
    __syncthreads();

    const int lane = threadIdx.x & 31, wid = threadIdx.x >> 5;
    const int t = lane & 3;
    const int r0 = wid * 16 + (lane >> 2), r1 = r0 + 8;
    const int b00 = (r0 / 20) * 336 + (r0 % 20) * 4 + 2 * t;
    const int b01 = (r1 / 20) * 336 + (r1 % 20) * 4 + 2 * t;
    const u32* wlane = wfu + lane * 2;

    float acc[2][4][4];
    #pragma unroll
    for (int nt = 0; nt < 4; nt++) {
        int oc = nt * 8 + t * 2;
        float b0 = bias[oc], b1 = bias[oc + 1];
        #pragma unroll
        for (int im = 0; im < 2; im++) {
            acc[im][nt][0] = b0; acc[im][nt][1] = b1;
            acc[im][nt][2] = b0; acc[im][nt][3] = b1;
        }
    }
    u32 a0[4], a1[4];
    uint2 bv[4];
    a0[0] = *(const u32*)&simg[b00];
    a0[1] = *(const u32*)&simg[b01];
    a0[2] = *(const u32*)&simg[84 + b00];
    a0[3] = *(const u32*)&simg[84 + b01];
    a1[0] = *(const u32*)&simg[6720 + b00];
    a1[1] = *(const u32*)&simg[6720 + b01];
    a1[2] = *(const u32*)&simg[6720 + 84 + b00];
    a1[3] = *(const u32*)&simg[6720 + 84 + b01];
    #pragma unroll
    for (int nt = 0; nt < 4; nt++)
        bv[nt] = *(const uint2*)&wlane[nt * 64];

    #pragma unroll
    for (int c = 0; c < 16; c++) {
        u32 na0[4], na1[4];
        uint2 nbv[4];
        if (c < 15) {
            const int o = ((c + 1) >> 2) * 1680 + ((c + 1) & 3) * 168;
            na0[0] = *(const u32*)&simg[o + b00];
            na0[1] = *(const u32*)&simg[o + b01];
            na0[2] = *(const u32*)&simg[o + 84 + b00];
            na0[3] = *(const u32*)&simg[o + 84 + b01];
            na1[0] = *(const u32*)&simg[6720 + o + b00];
            na1[1] = *(const u32*)&simg[6720 + o + b01];
            na1[2] = *(const u32*)&simg[6720 + o + 84 + b00];
            na1[3] = *(const u32*)&simg[6720 + o + 84 + b01];
            #pragma unroll
            for (int nt = 0; nt < 4; nt++)
                nbv[nt] = *(const uint2*)&wlane[((c + 1) * 4 + nt) * 64];
        }
        #pragma unroll
        for (int nt = 0; nt < 4; nt++) {
            u32 b[2] = {bv[nt].x, bv[nt].y};
            mmabf(acc[0][nt], a0, b);
            mmabf(acc[1][nt], a1, b);
        }
        if (c < 15) {
            #pragma unroll
            for (int q = 0; q < 4; q++) { a0[q] = na0[q]; a1[q] = na1[q]; }
            #pragma unroll
            for (int nt = 0; nt < 4; nt++) bv[nt] = nbv[nt];
        }
    }
    #pragma unroll
    for (int im = 0; im < 2; im++) {
        const int img = p + im * 512;
        __nv_bfloat16* ob = out + (size_t)img * 12800 + oyg * 80;
        #pragma unroll
        for (int nt = 0; nt < 4; nt++) {
            int oc = nt * 8 + t * 2;
            __nv_bfloat16* p0 = ob + (size_t)oc * 400;
            p0[r0]       = __float2bfloat16(fmaxf(acc[im][nt][0], 0.0f));
            p0[400 + r0] = __float2bfloat16(fmaxf(acc[im][nt][1], 0.0f));
            p0[r1]       = __float2bfloat16(fmaxf(acc[im][nt][2], 0.0f));
            p0[400 + r1] = __float2bfloat16(fmaxf(acc[im][nt][3], 0.0f));
        }
    }
}

// ---------------------------------------------------------------------------
// conv2: grid (512 pairs, 2 oc-halves), 192 thr (6 warps, M=32/warp).
// cp.async staging + gmem B shared across 2 row-groups. 4 blocks/SM.
// ---------------------------------------------------------------------------
__global__ void __launch_bounds__(192, 4)
conv2_mma(const __nv_bfloat16* __restrict__ a1,
          const u32* __restrict__ wfu,
          const float* __restrict__ bias,
          __nv_bfloat16* __restrict__ out) {
    extern __shared__ char smc[];
    __nv_bfloat16* sin = (__nv_bfloat16*)smc;      // 25600 bf16
    const int p = blockIdx.x, q = blockIdx.y;
    const uint4* src = (const uint4*)(a1 + (size_t)p * 25600);
    const u32 sb0 = smem_u32(smc);
    for (int i = threadIdx.x; i < 3200; i += 192)
        cpa16(sb0 + (u32)i * 16u, &src[i]);
    cpa_commit();
    cpa_wait<0>();
    __syncthreads();

    const int lane = threadIdx.x & 31, wid = threadIdx.x >> 5;
    const int t = lane & 3;
    const int toff = (t >> 1) * 20 + (t & 1) * 2;
    const int rb = wid * 32 + (lane >> 2);
    int rr[4] = {rb, rb + 8, rb + 16, rb + 24};
    int AO[4], IM[4], PX[4];
    #pragma unroll
    for (int k = 0; k < 4; k++) {
        int gg = (rr[k] < 162) ? rr[k] : 161;
        IM[k] = gg / 81; PX[k] = gg % 81;
        AO[k] = IM[k] * 12800 + (PX[k] / 9) * 40 + (PX[k] % 9) * 2 + toff;
    }
    const u32* wlane = wfu + (size_t)q * 4 * 64 + lane * 2;

    float acc[2][4][4];
    #pragma unroll
    for (int nt = 0; nt < 4; nt++) {
        int oc = q * 32 + nt * 8 + t * 2;
        float b0 = bias[oc], b1 = bias[oc + 1];
        #pragma unroll
        for (int G = 0; G < 2; G++) {
            acc[G][nt][0] = b0; acc[G][nt][1] = b1;
            acc[G][nt][2] = b0; acc[G][nt][3] = b1;
        }
    }

    u32 aG0[4], aG1[4];
    uint2 bv[4];
    aG0[0] = *(const u32*)&sin[AO[0]];
    aG0[1] = *(const u32*)&sin[AO[1]];
    aG0[2] = *(const u32*)&sin[40 + AO[0]];
    aG0[3] = *(const u32*)&sin[40 + AO[1]];
    aG1[0] = *(const u32*)&sin[AO[2]];
    aG1[1] = *(const u32*)&sin[AO[3]];
    aG1[2] = *(const u32*)&sin[40 + AO[2]];
    aG1[3] = *(const u32*)&sin[40 + AO[3]];
    #pragma unroll
    for (int nt = 0; nt < 4; nt++)
        bv[nt] = *(const uint2*)&wlane[nt * 64];

    #pragma unroll 8
    for (int ic = 0; ic < 32; ic++) {
        u32 na0[4], na1[4];
        uint2 nbv[4];
        if (ic < 31) {
            const int o = (ic + 1) * 400;
            na0[0] = *(const u32*)&sin[o + AO[0]];
            na0[1] = *(const u32*)&sin[o + AO[1]];
            na0[2] = *(const u32*)&sin[o + 40 + AO[0]];
            na0[3] = *(const u32*)&sin[o + 40 + AO[1]];
            na1[0] = *(const u32*)&sin[o + AO[2]];
            na1[1] = *(const u32*)&sin[o + AO[3]];
            na1[2] = *(const u32*)&sin[o + 40 + AO[2]];
            na1[3] = *(const u32*)&sin[o + 40 + AO[3]];
            #pragma unroll
            for (int nt = 0; nt < 4; nt++)
                nbv[nt] = *(const uint2*)&wlane[((ic + 1) * 8 + nt) * 64];
        }
        #pragma unroll
        for (int nt = 0; nt < 4; nt++) {
            u32 b[2] = {bv[nt].x, bv[nt].y};
            mmabf(acc[0][nt], aG0, b);
            mmabf(acc[1][nt], aG1, b);
        }
        if (ic < 31) {
            #pragma unroll
            for (int k = 0; k < 4; k++) { aG0[k] = na0[k]; aG1[k] = na1[k]; }
            #pragma unroll
            for (int nt = 0; nt < 4; nt++) bv[nt] = nbv[nt];
        }
    }
    #pragma unroll
    for (int G = 0; G < 2; G++) {
        #pragma unroll
        for (int nt = 0; nt < 4; nt++) {
            int oc = q * 32 + nt * 8 + t * 2;
            const int k0 = G * 2, k1 = G * 2 + 1;
            if (rr[k0] < 162)
                *(u32*)&out[((size_t)(p * 2 + IM[k0]) * 81 + PX[k0]) * 64 + oc] =
                    packbf(fmaxf(acc[G][nt][0], 0.0f), fmaxf(acc[G][nt][1], 0.0f));
            if (rr[k1] < 162)
                *(u32*)&out[((size_t)(p * 2 + IM[k1]) * 81 + PX[k1]) * 64 + oc] =
                    packbf(fmaxf(acc[G][nt][2], 0.0f), fmaxf(acc[G][nt][3], 0.0f));
        }
    }
}

// ---------------------------------------------------------------------------
// conv3: grid (512, 2 oc-halves), 128 thr (4 warps, M=32/warp).
// LDSM A x2 groups sharing gmem-B frags. 5 blocks/SM.
// ---------------------------------------------------------------------------
__global__ void __launch_bounds__(128, 5)
conv3_mma(const __nv_bfloat16* __restrict__ a2n,
          const u32* __restrict__ wfu,
          const float* __restrict__ bias,
          __nv_bfloat16* __restrict__ feat) {
    extern __shared__ char smc[];
    __nv_bfloat16* sin = (__nv_bfloat16*)smc;      // 2*81*72 bf16
    const int q = blockIdx.y;
    const int imgb = blockIdx.x * 2;
    for (int i = threadIdx.x; i < 1296; i += 128) {
        int im = i / 648, r = i % 648;
        int px = r >> 3, qq = r & 7;
        *((uint4*)&sin[im * 5832 + px * 72]       + qq) =
        *((const uint4*)&a2n[((size_t)(imgb + im) * 81 + px) * 64] + qq);
    }
    __syncthreads();

    const int lane = threadIdx.x & 31, wid = threadIdx.x >> 5;
    const int t = lane & 3;
    const u32 sb = smem_u32(smc);
    u32 laG[2];
    #pragma unroll
    for (int G = 0; G < 2; G++) {
        int r = wid * 32 + G * 16 + (lane & 15);
        if (r > 97) r = 97;
        int im = r / 49, lp = r % 49;
        laG[G] = sb + (u32)(im * 11664 + ((lp / 7) * 9 + lp % 7) * 144)
                    + ((lane & 16) ? 16u : 0u);
    }
    const u32* wlane = wfu + (size_t)q * 4 * 64 + lane * 2;

    float acc[2][4][4];
    #pragma unroll
    for (int nt = 0; nt < 4; nt++) {
        int oc = q * 32 + nt * 8 + t * 2;
        float b0 = bias[oc], b1 = bias[oc + 1];
        #pragma unroll
        for (int G = 0; G < 2; G++) {
            acc[G][nt][0] = b0; acc[G][nt][1] = b1;
            acc[G][nt][2] = b0; acc[G][nt][3] = b1;
        }
    }

    u32 a0[4], a1[4];
    uint2 bv[4];
    ldsm4(a0, laG[0]);
    ldsm4(a1, laG[1]);
    #pragma unroll
    for (int nt = 0; nt < 4; nt++)
        bv[nt] = *(const uint2*)&wlane[nt * 64];

    #pragma unroll
    for (int c = 0; c < 36; c++) {
        u32 na0[4], na1[4];
        uint2 nbv[4];
        if (c < 35) {
            const int pp = (c + 1) >> 2, icc = (c + 1) & 3;
            const u32 off = (u32)(((pp / 3) * 9 + (pp % 3)) * 144 + icc * 32);
            ldsm4(na0, laG[0] + off);
            ldsm4(na1, laG[1] + off);
            #pragma unroll
            for (int nt = 0; nt < 4; nt++)
                nbv[nt] = *(const uint2*)&wlane[((c + 1) * 8 + nt) * 64];
        }
        #pragma unroll
        for (int nt = 0; nt < 4; nt++) {
            u32 b[2] = {bv[nt].x, bv[nt].y};
            mmabf(acc[0][nt], a0, b);
            mmabf(acc[1][nt], a1, b);
        }
        if (c < 35) {
            #pragma unroll
            for (int k = 0; k < 4; k++) { a0[k] = na0[k]; a1[k] = na1[k]; }
            #pragma unroll
            for (int nt = 0; nt < 4; nt++) bv[nt] = nbv[nt];
        }
    }
    #pragma unroll
    for (int G = 0; G < 2; G++) {
        const int r0 = wid * 32 + G * 16 + (lane >> 2), r1 = r0 + 8;
        const int g0 = (r0 < 98) ? r0 : 97, g1 = (r1 < 98) ? r1 : 97;
        const int im0 = g0 / 49, lp0 = g0 % 49;
        const int im1 = g1 / 49, lp1 = g1 % 49;
        #pragma unroll
        for (int nt = 0; nt < 4; nt++) {
            int oc = q * 32 + nt * 8 + t * 2;
            if (r0 < 98) {
                __nv_bfloat16* fb = feat + (size_t)(imgb + im0) * 3136 + oc * 49 + lp0;
                fb[0]  = __float2bfloat16(fmaxf(acc[G][nt][0], 0.0f));
                fb[49] = __float2bfloat16(fmaxf(acc[G][nt][1], 0.0f));
            }
            if (r1 < 98) {
                __nv_bfloat16* fb = feat + (size_t)(imgb + im1) * 3136 + oc * 49 + lp1;
                fb[0]  = __float2bfloat16(fmaxf(acc[G][nt][2], 0.0f));
                fb[49] = __float2bfloat16(fmaxf(acc[G][nt][3], 0.0f));
            }
        }
    }
}

// ---------------------------------------------------------------------------
// FC (bf16 mma): [1024,3136]@[3136,256], split-K 4, cp.async double-buffered.
// ---------------------------------------------------------------------------
__global__ void fc_mma(const __nv_bfloat16* __restrict__ feat,
                       const u32* __restrict__ wfu,
                       float* __restrict__ part) {
    extern __shared__ char smc[];
    const int mb = blockIdx.x, nb = blockIdx.y, z = blockIdx.z;
    const int m0b = mb * 128;
    const int lane = threadIdx.x & 31, wid = threadIdx.x >> 5;
    const int t = lane & 3, g = lane >> 2;
    const u32 sbase = smem_u32(smc);

    #define FC_STAGE(IT, BUF) do {                                            \
        const int kbase_ = z * 784 + (IT) * 112;                              \
        const int cbase_ = z * 49 + (IT) * 7;                                 \
        const u32 aoff_ = sbase + (BUF) * 30720u;                             \
        for (int i = threadIdx.x; i < 1792; i += 256) {                       \
            int row_ = i / 14, seg_ = i % 14;                                 \
            cpa16(aoff_ + (u32)(row_ * 120 + seg_ * 8) * 2u,                  \
                  &feat[(size_t)(m0b + row_) * 3136 + kbase_ + seg_ * 8]);    \
        }                                                                     \
        const u32 boff_ = sbase + 61440u + (BUF) * 14336u;                    \
        for (int i = threadIdx.x; i < 896; i += 256) {                        \
            int cn_ = i >> 4, cl_ = cn_ >> 3, ntl_ = cn_ & 7;                 \
            cpa16(boff_ + (u32)i * 16u,                                       \
                  &wfu[((size_t)(cbase_ + cl_) * 32 + nb * 8 + ntl_) * 64     \
                       + (i & 15) * 4]);                                      \
        }                                                                     \
    } while (0)

    float acc[8][4] = {};
    FC_STAGE(0, 0);
    cpa_commit();
    for (int it = 0; it < 7; it++) {
        if (it < 6) {
            FC_STAGE(it + 1, (it + 1) & 1);
            cpa_commit();
            cpa_wait<1>();
        } else {
            cpa_wait<0>();
        }
        __syncthreads();
        const __nv_bfloat16* sA = (const __nv_bfloat16*)(smc + (it & 1) * 30720);
        const u32* sB = (const u32*)(smc + 61440 + (it & 1) * 14336);
        #pragma unroll
        for (int c_l = 0; c_l < 7; c_l++) {
            const int ra = (wid * 16 + g) * 120 + c_l * 16 + 2 * t;
            u32 a[4];
            a[0] = *(const u32*)&sA[ra];
            a[1] = *(const u32*)&sA[ra + 8 * 120];
            a[2] = *(const u32*)&sA[ra + 8];
            a[3] = *(const u32*)&sA[ra + 8 * 120 + 8];
            const u32* wb = sB + c_l * 512 + lane * 2;
            #pragma unroll
            for (int nt = 0; nt < 8; nt++) {
                uint2 bv = *(const uint2*)&wb[nt * 64];
                u32 b[2] = {bv.x, bv.y};
                mmabf(acc[nt], a, b);
            }
        }
        __syncthreads();
    }
    #undef FC_STAGE

    float* pb = part + (size_t)z * 262144;
    const int mr0 = m0b + wid * 16 + g, mr1 = mr0 + 8;
    #pragma unroll
    for (int nt = 0; nt < 8; nt++) {
        int col = nb * 64 + nt * 8 + 2 * t;
        *(float2*)&pb[(size_t)mr0 * 256 + col] = make_float2(acc[nt][0], acc[nt][1]);
        *(float2*)&pb[(size_t)mr1 * 256 + col] = make_float2(acc[nt][2], acc[nt][3]);
    }
}

// ---------------------------------------------------------------------------
// head GEMM bodies
// ---------------------------------------------------------------------------
__device__ void head_bodyP(const float* __restrict__ part, int rowOff,
                           const float* __restrict__ fcb,
                           const u32* __restrict__ wfu,
                           const float* __restrict__ bias,
                           float* __restrict__ C,
                           int NTg, int mb, int nb) {
    extern __shared__ char smc[];
    __nv_bfloat16* sA = (__nv_bfloat16*)smc;
    u32* sB = (u32*)(smc + 34816);
    const int m0b = mb * 128;
    const int N = NTg * 8;
    const int lane = threadIdx.x & 31, wid = threadIdx.x >> 5;
    const int t = lane & 3, g = lane >> 2;

    float acc[8][4] = {};
    #pragma unroll
    for (int it = 0; it < 2; it++) {
        const int kbase = it * 128;
        __syncthreads();
        for (int i = threadIdx.x; i < 4096; i += 256) {
            int row = i >> 5, seg = i & 31;
            size_t idx = (size_t)(rowOff + m0b + row) * 256 + kbase + seg * 4;
            float4 v = *(const float4*)&fcb[kbase + seg * 4];
            float4 p0 = *(const float4*)&part[idx];
            float4 p1 = *(const float4*)&part[262144 + idx];
            float4 p2 = *(const float4*)&part[524288 + idx];
            float4 p3 = *(const float4*)&part[786432 + idx];
            v.x = fmaxf(v.x + p0.x + p1.x + p2.x + p3.x, 0.0f);
            v.y = fmaxf(v.y + p0.y + p1.y + p2.y + p3.y, 0.0f);
            v.z = fmaxf(v.z + p0.z + p1.z + p2.z + p3.z, 0.0f);
            v.w = fmaxf(v.w + p0.w + p1.w + p2.w + p3.w, 0.0f);
            u32* d = (u32*)&sA[row * 136 + seg * 4];
            d[0] = packbf(v.x, v.y);
            d[1] = packbf(v.z, v.w);
        }
        for (int i = threadIdx.x; i < 1024; i += 256) {
            int cn = i >> 4, c_l = cn >> 3, ntl = cn & 7;
            ((uint4*)sB)[i] =
                *(const uint4*)&wfu[(((it * 8 + c_l) * NTg) + nb * 8 + ntl) * 64 + (i & 15) * 4];
        }
        __syncthreads();
        #pragma unroll
        for (int c_l = 0; c_l < 8; c_l++) {
            const int ra = (wid * 16 + g) * 136 + c_l * 16 + 2 * t;
            u32 a[4];
            a[0] = *(const u32*)&sA[ra];
            a[1] = *(const u32*)&sA[ra + 8 * 136];
            a[2] = *(const u32*)&sA[ra + 8];
            a[3] = *(const u32*)&sA[ra + 8 * 136 + 8];
            const u32* wb = sB + c_l * 512 + lane * 2;
            #pragma unroll
            for (int nt = 0; nt < 8; nt++) {
                uint2 bv = *(const uint2*)&wb[nt * 64];
                u32 b[2] = {bv.x, bv.y};
                mmabf(acc[nt], a, b);
            }
        }
    }
    const int mr0 = m0b + wid * 16 + g, mr1 = mr0 + 8;
    #pragma unroll
    for (int nt = 0; nt < 8; nt++) {
        int col = nb * 64 + nt * 8 + 2 * t;
        float b0 = bias[col], b1 = bias[col + 1];
        float v00 = fmaxf(acc[nt][0] + b0, 0.0f), v01 = fmaxf(acc[nt][1] + b1, 0.0f);
        float v10 = fmaxf(acc[nt][2] + b0, 0.0f), v11 = fmaxf(acc[nt][3] + b1, 0.0f);
        *(float2*)&C[(size_t)mr0 * N + col] = make_float2(v00, v01);
        *(float2*)&C[(size_t)mr1 * N + col] = make_float2(v10, v11);
    }
}

__device__ void head_body(const float* __restrict__ A,
                          const u32* __restrict__ wfu,
                          const float* __restrict__ bias,
                          float* __restrict__ C,
                          int NTg, int doRelu, int mb, int nb) {
    extern __shared__ char smc[];
    __nv_bfloat16* sA = (__nv_bfloat16*)smc;
    u32* sB = (u32*)(smc + 34816);
    const int m0b = mb * 128;
    const int N = NTg * 8;
    const int lane = threadIdx.x & 31, wid = threadIdx.x >> 5;
    const int t = lane & 3, g = lane >> 2;

    float acc[8][4] = {};
    #pragma unroll
    for (int it = 0; it < 2; it++) {
        const int kbase = it * 128;
        __syncthreads();
        for (int i = threadIdx.x; i < 4096; i += 256) {
            int row = i >> 5, seg = i & 31;
            float4 v = *(const float4*)&A[(size_t)(m0b + row) * 256 + kbase + seg * 4];
            u32* d = (u32*)&sA[row * 136 + seg * 4];
            d[0] = packbf(v.x, v.y);
            d[1] = packbf(v.z, v.w);
        }
        for (int i = threadIdx.x; i < 1024; i += 256) {
            int cn = i >> 4, c_l = cn >> 3, ntl = cn & 7;
            ((uint4*)sB)[i] =
                *(const uint4*)&wfu[(((it * 8 + c_l) * NTg) + nb * 8 + ntl) * 64 + (i & 15) * 4];
        }
        __syncthreads();
        #pragma unroll
        for (int c_l = 0; c_l < 8; c_l++) {
            const int ra = (wid * 16 + g) * 136 + c_l * 16 + 2 * t;
            u32 a[4];
            a[0] = *(const u32*)&sA[ra];
            a[1] = *(const u32*)&sA[ra + 8 * 136];
            a[2] = *(const u32*)&sA[ra + 8];
            a[3] = *(const u32*)&sA[ra + 8 * 136 + 8];
            const u32* wb = sB + c_l * 512 + lane * 2;
            #pragma unroll
            for (int nt = 0; nt < 8; nt++) {
                uint2 bv = *(const uint2*)&wb[nt * 64];
                u32 b[2] = {bv.x, bv.y};
                mmabf(acc[nt], a, b);
            }
        }
    }
    const int mr0 = m0b + wid * 16 + g, mr1 = mr0 + 8;
    #pragma unroll
    for (int nt = 0; nt < 8; nt++) {
        int col = nb * 64 + nt * 8 + 2 * t;
        float b0 = bias[col], b1 = bias[col + 1];
        float v00 = acc[nt][0] + b0, v01 = acc[nt][1] + b1;
        float v10 = acc[nt][2] + b0, v11 = acc[nt][3] + b1;
        if (doRelu) {
            v00 = fmaxf(v00, 0.0f); v01 = fmaxf(v01, 0.0f);
            v10 = fmaxf(v10, 0.0f); v11 = fmaxf(v11, 0.0f);
        }
        *(float2*)&C[(size_t)mr0 * N + col] = make_float2(v00, v01);
        *(float2*)&C[(size_t)mr1 * N + col] = make_float2(v10, v11);
    }
}

__global__ void headA(const float* __restrict__ part, const float* __restrict__ fcb,
                      const u32* __restrict__ we1, const float* __restrict__ e1b,
                      float* __restrict__ h1,
                      const u32* __restrict__ wp1, const float* __restrict__ pb1,
                      float* __restrict__ hp) {
    int bid = blockIdx.x;
    if (bid < 32) head_bodyP(part, 0, fcb, we1, e1b, h1, 32, bid >> 2, bid & 3);
    else {
        bid -= 32;
        head_bodyP(part, 512, fcb, wp1, pb1, hp, 32, bid >> 2, bid & 3);
    }
}

__global__ void headB(const float* __restrict__ h1,
                      const u32* __restrict__ we2, const float* __restrict__ e2b,
                      float* __restrict__ phi,
                      const float* __restrict__ hp,
                      const float* __restrict__ pw2, const float* __restrict__ pb2,
                      float* __restrict__ cy) {
    int bid = blockIdx.x;
    if (bid < 8) {
        head_body(h1, we2, e2b, phi, 8, 0, bid, 0);
    } else {
        const int gw = (bid - 8) * 8 + (threadIdx.x >> 5);
        const int lane = threadIdx.x & 31;
        float s = 0.0f;
        for (int k = lane; k < 256; k += 32)
            s = fmaf(hp[(size_t)gw * 256 + k], pw2[k], s);
        #pragma unroll
        for (int off = 16; off > 0; off >>= 1) s += __shfl_xor_sync(0xffffffffu, s, off);
        if (lane == 0) cy[gw] = s + pb2[0];
    }
}

// ---------------------------------------------------------------------------
// logits: 4 rows/block (grid 128), float4 y loads + fused final loss.
// ---------------------------------------------------------------------------
__global__ void logits_kernel(const float* __restrict__ phi,
                              const float* __restrict__ cy,
                              float* __restrict__ lse,
                              float* __restrict__ diag,
                              float* __restrict__ out) {
    const int i0 = blockIdx.x * 4;
    __shared__ float sx[4][64];
    __shared__ float red[256];
    __shared__ float red2[256];
    __shared__ float sdiag[4];
    __shared__ int isLast;
    const int tid = threadIdx.x;
    sx[tid >> 6][tid & 63] = phi[(size_t)(i0 + (tid >> 6)) * 64 + (tid & 63)];
    __syncthreads();

    float lg[2][4];
    #pragma unroll
    for (int rep = 0; rep < 2; rep++) {
        const int j = tid + rep * 256;
        const float4* y4 = (const float4*)(phi + (size_t)(512 + j) * 64);
        float mx[4] = {0.f, 0.f, 0.f, 0.f}, ss[4] = {0.f, 0.f, 0.f, 0.f};
        #pragma unroll
        for (int k4 = 0; k4 < 8; k4++) {
            const float4 v = y4[k4];
            #pragma unroll
            for (int r = 0; r < 4; r++) {
                float d0 = sx[r][k4 * 4 + 0] - v.x;
                float d1 = sx[r][k4 * 4 + 1] - v.y;
                float d2 = sx[r][k4 * 4 + 2] - v.z;
                float d3 = sx[r][k4 * 4 + 3] - v.w;
                mx[r] = fmaxf(mx[r], fmaxf(fmaxf(d0, d1), fmaxf(d2, d3)));
            }
        }
        #pragma unroll
        for (int k4 = 8; k4 < 16; k4++) {
            const float4 v = y4[k4];
            #pragma unroll
            for (int r = 0; r < 4; r++) {
                float d0 = sx[r][k4 * 4 + 0] - v.x;
                float d1 = sx[r][k4 * 4 + 1] - v.y;
                float d2 = sx[r][k4 * 4 + 2] - v.z;
                float d3 = sx[r][k4 * 4 + 3] - v.w;
                ss[r] = fmaf(d0, d0, ss[r]);
                ss[r] = fmaf(d1, d1, ss[r]);
                ss[r] = fmaf(d2, d2, ss[r]);
                ss[r] = fmaf(d3, d3, ss[r]);
            }
        }
        const float cyj = cy[j];
        #pragma unroll
        for (int r = 0; r < 4; r++) {
            lg[rep][r] = cyj - (mx[r] + sqrtf(ss[r] + 1e-8f));
            if (j == i0 + r) sdiag[r] = lg[rep][r];
        }
    }
    #pragma unroll
    for (int r = 0; r < 4; r++) {
        __syncthreads();
        red[tid] = fmaxf(lg[0][r], lg[1][r]);
        __syncthreads();
        for (int s = 128; s > 0; s >>= 1) {
            if (tid < s) red[tid] = fmaxf(red[tid], red[tid + s]);
            __syncthreads();
        }
        const float rowmax = red[0];
        __syncthreads();
        red[tid] = expf(lg[0][r] - rowmax) + expf(lg[1][r] - rowmax);
        __syncthreads();
        for (int s = 128; s > 0; s >>= 1) {
            if (tid < s) red[tid] += red[tid + s];
            __syncthreads();
        }
        if (tid == 0) {
            lse[i0 + r] = rowmax + logf(red[0]);
            diag[i0 + r] = sdiag[r];
        }
    }

    __threadfence();
    if (tid == 0) isLast = (atomicAdd(&g_done, 1) == 127) ? 1 : 0;
    __syncthreads();
    if (isLast) {
        __threadfence();
        float s1 = 0.0f, s2 = 0.0f;
        for (int i = tid; i < 512; i += 256) {
            const float l = lse[i];
            s1 += l - diag[i];
            const float u = l + 1e-6f;
            s2 = fmaf(u, u, s2);
        }
        red[tid] = s1; red2[tid] = s2;
        __syncthreads();
        for (int s = 128; s > 0; s >>= 1) {
            if (tid < s) { red[tid] += red[tid + s]; red2[tid] += red2[tid + s]; }
            __syncthreads();
        }
        if (tid == 0) {
            out[0] = red[0] * (1.0f / 512.0f) + 0.1f * red2[0] * (1.0f / 512.0f);
            g_done = 0;
        }
    }
}

// ---------------------------------------------------------------------------
// Host launcher
// ---------------------------------------------------------------------------
extern "C" void kernel_launch(void* const* d_in, const int* in_sizes, int n_in,
                              void* d_out, int out_size) {
    const float* curr = (const float*)d_in[0];
    const float* next = (const float*)d_in[1];
    const float* c1w = (const float*)d_in[2];
    const float* c1b = (const float*)d_in[3];
    const float* c2w = (const float*)d_in[4];
    const float* c2b = (const float*)d_in[5];
    const float* c3w = (const float*)d_in[6];
    const float* c3b = (const float*)d_in[7];
    const float* fcw = (const float*)d_in[8];
    const float* fcb = (const float*)d_in[9];
    const float* e1w = (const float*)d_in[10];
    const float* e1b = (const float*)d_in[11];
    const float* e2w = (const float*)d_in[12];
    const float* e2b = (const float*)d_in[13];
    const float* pw1 = (const float*)d_in[14];
    const float* pb1 = (const float*)d_in[15];
    const float* pw2 = (const float*)d_in[16];
    const float* pb2 = (const float*)d_in[17];

    u32 *p_w1f, *p_w2f, *p_w3f, *p_wfc, *p_we1, *p_we2, *p_wp1;
    __nv_bfloat16 *p_a1, *p_a2n, *p_feat;
    float *p_h1, *p_phi, *p_hp, *p_cy, *p_lse, *p_diag, *p_part;
    cudaGetSymbolAddress((void**)&p_w1f, g_w1f);
    cudaGetSymbolAddress((void**)&p_w2f, g_w2f);
    cudaGetSymbolAddress((void**)&p_w3f, g_w3f);
    cudaGetSymbolAddress((void**)&p_wfc, g_wfc);
    cudaGetSymbolAddress((void**)&p_we1, g_we1);
    cudaGetSymbolAddress((void**)&p_we2, g_we2);
    cudaGetSymbolAddress((void**)&p_wp1, g_wp1);
    cudaGetSymbolAddress((void**)&p_a1, g_a1);
    cudaGetSymbolAddress((void**)&p_a2n, g_a2n);
    cudaGetSymbolAddress((void**)&p_feat, g_feat);
    cudaGetSymbolAddress((void**)&p_h1, g_h1);
    cudaGetSymbolAddress((void**)&p_phi, g_phi);
    cudaGetSymbolAddress((void**)&p_hp, g_hp);
    cudaGetSymbolAddress((void**)&p_cy, g_cy);
    cudaGetSymbolAddress((void**)&p_lse, g_lse);
    cudaGetSymbolAddress((void**)&p_diag, g_diag);
    cudaGetSymbolAddress((void**)&p_part, g_part);

    const int SM1 = 26880;
    const int SM2 = 51200;
    const int SM3 = 23328;
    const int SMF = 90112;
    const int SMH = 34816 + 4096 * 4;
    cudaFuncSetAttribute(conv1_mma, cudaFuncAttributeMaxDynamicSharedMemorySize, SM1);
    cudaFuncSetAttribute(conv2_mma, cudaFuncAttributeMaxDynamicSharedMemorySize, SM2);
    cudaFuncSetAttribute(conv3_mma, cudaFuncAttributeMaxDynamicSharedMemorySize, SM3);
    cudaFuncSetAttribute(fc_mma, cudaFuncAttributeMaxDynamicSharedMemorySize, SMF);
    cudaFuncSetAttribute(headA, cudaFuncAttributeMaxDynamicSharedMemorySize, SMH);
    cudaFuncSetAttribute(headB, cudaFuncAttributeMaxDynamicSharedMemorySize, SMH);

    prep_all<<<538, 256>>>(c1w, c2w, c3w, fcw, e1w, e2w, pw1,
                           p_w1f, p_w2f, p_w3f, p_wfc, p_we1, p_we2, p_wp1);

    conv1_mma<<<dim3(512, 5), 160, SM1>>>(curr, next, p_w1f, c1b, p_a1);
    conv2_mma<<<dim3(512, 2), 192, SM2>>>(p_a1, p_w2f, c2b, p_a2n);
    conv3_mma<<<dim3(512, 2), 128, SM3>>>(p_a2n, p_w3f, c3b, p_feat);

    fc_mma<<<dim3(8, 4, 4), 256, SMF>>>(p_feat, p_wfc, p_part);

    headA<<<48, 256, SMH>>>(p_part, fcb, p_we1, e1b, p_h1, p_wp1, pb1, p_hp);
    headB<<<72, 256, SMH>>>(p_h1, p_we2, e2b, p_phi, p_hp, pw2, pb2, p_cy);

    logits_kernel<<<128, 256>>>(p_phi, p_cy, p_lse, p_diag, (float*)d_out);
}